// round 6
// baseline (speedup 1.0000x reference)
#include <cuda_runtime.h>
#include <cuda_bf16.h>
#include <cstdint>

// Problem constants (SheafGluingPoly: B=4, M=50000, D=8, E=1600000, POLY_K=3, LAM=1)
#define B_CONST 4
#define D_CONST 8
#define MAX_MBD 1600000   // B*M*D
#define MAX_E   1600000

// Scratch: ping-pong vertex state in transposed [m][b][d] layout (128B/vertex),
// plus packed (src,dst) pairs.
__device__ float g_bufA[MAX_MBD];
__device__ float g_bufB[MAX_MBD];
__device__ int2  g_pair[MAX_E];

// ---------------------------------------------------------------------------
// init (fused with pair packing):
//   v(A) = transpose(c0), out = pc[0]*c0, acc(B) = 0, pair[e] = (src,dst)
// ---------------------------------------------------------------------------
__global__ void init_kernel(const float* __restrict__ c0,
                            const int*   __restrict__ src,
                            const int*   __restrict__ dst,
                            const float* __restrict__ pc,
                            float* __restrict__ out,
                            float* __restrict__ v,
                            float* __restrict__ accz,
                            int2*  __restrict__ pair,
                            int M, int E)
{
    int i = blockIdx.x * blockDim.x + threadIdx.x;
    int n = M * 32;
    if (i < n) {
        int m = i >> 5;
        int t = i & 31;
        int b = t >> 3;
        int d = t & 7;
        int src_idx = (b * M + m) * 8 + d;   // [b][m][d] layout of c0 / out
        float val = c0[src_idx];
        v[i] = val;
        out[src_idx] = pc[0] * val;
        accz[i] = 0.0f;
    }
    if (i < E) {
        pair[i] = make_int2(src[i], dst[i]);
    }
}

// ---------------------------------------------------------------------------
// edge kernel: one warp per edge. lane t = b*8 + d (d = d2 d1 d0).
// Register k = (k2, k01) holds column d of row rho(k,d) = ((k01 ^ d01) | k2*4):
//   addr = base + rho*32 + d*4 ; for fixed k, bit7 (=k2) is constant across
//   lanes -> every LDG touches exactly ONE 128B line.
// Reduction (stage-4 FIRST for register-level parallelism):
//   z[k] = S[k]*ps - D[k]*pd
//   stage4: z[k] += shfl_xor(z[k],4)        (rho independent of d2; 8 indep)
//   stage2: z[k] += shfl_xor(z[k^2],2), k in {0,1,4,5}   (4 indep)
//   stage1: z[k] += shfl_xor(z[k^1],1), k in {0,4}       (2 indep)
//   -> R0 = r[d01], R1 = r[d01+4]  (full sums, at every lane)
// Allgather: r[(x^d01)|4*h] = shfl_xor(Rh, x); transpose matvec local.
//   acc[src][b][d] += cs ;  acc[dst][b][d] += -cd
// ---------------------------------------------------------------------------
__global__ void __launch_bounds__(256)
edge_kernel(const float* __restrict__ v,
            const int2*  __restrict__ pair,
            const float* __restrict__ Rsrc,
            const float* __restrict__ Rdst,
            float*       __restrict__ acc,
            int E)
{
    int e = (blockIdx.x * blockDim.x + threadIdx.x) >> 5;
    if (e >= E) return;
    int t = threadIdx.x & 31;
    int d = t & 7;

    int2 pr = __ldg(pair + e);

    const char* SB = (const char*)Rsrc + (size_t)e * 256;
    const char* DB = (const char*)Rdst + (size_t)e * 256;

    // o0 = d*4 + (d&3)*32 ; bits5-6 of o0 are d01, so XOR with x*32 gives
    // row (x ^ d01) with no carries.
    unsigned o0 = (unsigned)(d * 4 + (d & 3) * 32);

    float S[8], D[8];
#pragma unroll
    for (int x = 0; x < 4; x++) {
        unsigned ox = o0 ^ (unsigned)(x << 5);
        const float* pS = (const float*)(SB + ox);
        const float* pD = (const float*)(DB + ox);
        S[x]     = __ldg(pS);        // row (x^d01)     , col d
        S[x + 4] = __ldg(pS + 32);   // row (x^d01) + 4 , col d  (imm +128B)
        D[x]     = __ldg(pD);
        D[x + 4] = __ldg(pD + 32);
    }

    float ps = __ldg(v + pr.x * 32 + t);
    float pd = __ldg(v + pr.y * 32 + t);

    // z[k] = S[k]*ps - D[k]*pd
    float z[8];
#pragma unroll
    for (int k = 0; k < 8; k++) {
        z[k] = fmaf(S[k], ps, -(D[k] * pd));
    }

    const unsigned FULL = 0xffffffffu;

    // stage 4: 8 independent self-shfls (rho(k,d) invariant under d^4)
#pragma unroll
    for (int k = 0; k < 8; k++) {
        z[k] += __shfl_xor_sync(FULL, z[k], 4);
    }
    // stage 2: 4 independent
    z[0] += __shfl_xor_sync(FULL, z[2], 2);
    z[1] += __shfl_xor_sync(FULL, z[3], 2);
    z[4] += __shfl_xor_sync(FULL, z[6], 2);
    z[5] += __shfl_xor_sync(FULL, z[7], 2);
    // stage 1: 2 independent
    float R0 = z[0] + __shfl_xor_sync(FULL, z[1], 1);  // r[d01]
    float R1 = z[4] + __shfl_xor_sync(FULL, z[5], 1);  // r[d01 + 4]

    // allgather + transpose FMAs
    float cs = S[0] * R0;
    float cd = D[0] * R0;
    cs = fmaf(S[4], R1, cs);
    cd = fmaf(D[4], R1, cd);
#pragma unroll
    for (int x = 1; x < 4; x++) {
        float r0x = __shfl_xor_sync(FULL, R0, x);  // r[x^d01]
        float r1x = __shfl_xor_sync(FULL, R1, x);  // r[(x^d01)+4]
        cs = fmaf(S[x],     r0x, cs);
        cd = fmaf(D[x],     r0x, cd);
        cs = fmaf(S[x + 4], r1x, cs);
        cd = fmaf(D[x + 4], r1x, cd);
    }

    atomicAdd(acc + pr.x * 32 + t, cs);
    atomicAdd(acc + pr.y * 32 + t, -cd);
}

// ---------------------------------------------------------------------------
// update: out[b][m][d] += pc[k] * acc[m][b][d]; optionally zero the other buffer
// ---------------------------------------------------------------------------
__global__ void update_kernel(const float* __restrict__ acc,
                              const float* __restrict__ pc,
                              int k,
                              float* __restrict__ out,
                              float* __restrict__ zother,
                              int M)
{
    int i = blockIdx.x * blockDim.x + threadIdx.x;
    int n = M * 32;
    if (i >= n) return;
    int m = i >> 5;
    int t = i & 31;
    int b = t >> 3;
    int d = t & 7;
    float val = acc[i];
    int oi = (b * M + m) * 8 + d;
    out[oi] += pc[k] * val;
    if (zother) zother[i] = 0.0f;
}

// ---------------------------------------------------------------------------
// launch  (7 launches total; ncu -s 5 captures launch #6 = 3rd edge_kernel)
// ---------------------------------------------------------------------------
extern "C" void kernel_launch(void* const* d_in, const int* in_sizes, int n_in,
                              void* d_out, int out_size)
{
    const float* c0  = (const float*)d_in[0];
    const int*   src = (const int*)  d_in[1];
    const int*   dst = (const int*)  d_in[2];
    const float* Rs  = (const float*)d_in[3];
    const float* Rd  = (const float*)d_in[4];
    const float* pc  = (const float*)d_in[5];
    float* out = (float*)d_out;

    int E = in_sizes[1];
    int M = in_sizes[0] / (B_CONST * D_CONST);

    float* bufA;  float* bufB;  int2* pairp;
    cudaGetSymbolAddress((void**)&bufA,  g_bufA);
    cudaGetSymbolAddress((void**)&bufB,  g_bufB);
    cudaGetSymbolAddress((void**)&pairp, g_pair);

    int nV = M * 32;
    int tb = 256;
    int nInit = (nV > E) ? nV : E;
    int gI = (nInit + tb - 1) / tb;
    int gV = (nV + tb - 1) / tb;
    int gE = (E * 32 + tb - 1) / tb;

    init_kernel<<<gI, tb>>>(c0, src, dst, pc, out, bufA, bufB, pairp, M, E);

    // k = 1: B <- L(A); out += pc[1]*B; zero A
    edge_kernel<<<gE, tb>>>(bufA, pairp, Rs, Rd, bufB, E);
    update_kernel<<<gV, tb>>>(bufB, pc, 1, out, bufA, M);

    // k = 2: A <- L(B); out += pc[2]*A; zero B
    edge_kernel<<<gE, tb>>>(bufB, pairp, Rs, Rd, bufA, E);
    update_kernel<<<gV, tb>>>(bufA, pc, 2, out, bufB, M);

    // k = 3: B <- L(A); out += pc[3]*B
    edge_kernel<<<gE, tb>>>(bufA, pairp, Rs, Rd, bufB, E);
    update_kernel<<<gV, tb>>>(bufB, pc, 3, out, nullptr, M);
}

// round 7
// speedup vs baseline: 1.0434x; 1.0434x over previous
#include <cuda_runtime.h>
#include <cuda_bf16.h>
#include <cstdint>

// Problem constants (SheafGluingPoly: B=4, M=50000, D=8, E=1600000, POLY_K=3, LAM=1)
#define B_CONST 4
#define D_CONST 8
#define MAX_MBD 1600000   // B*M*D
#define MAX_E   1600000

#define EDGE_BLOCKS 1184  // ~8 blocks/SM on 148 SMs
#define EDGE_TPB    256

// Scratch: ping-pong vertex state in transposed [m][b][d] layout (128B/vertex),
// plus packed (src,dst) pairs.
__device__ float g_bufA[MAX_MBD];
__device__ float g_bufB[MAX_MBD];
__device__ int2  g_pair[MAX_E];

// ---------------------------------------------------------------------------
// init (fused with pair packing):
//   v(A) = transpose(c0), out = pc[0]*c0, acc(B) = 0, pair[e] = (src,dst)
// ---------------------------------------------------------------------------
__global__ void init_kernel(const float* __restrict__ c0,
                            const int*   __restrict__ src,
                            const int*   __restrict__ dst,
                            const float* __restrict__ pc,
                            float* __restrict__ out,
                            float* __restrict__ v,
                            float* __restrict__ accz,
                            int2*  __restrict__ pair,
                            int M, int E)
{
    int i = blockIdx.x * blockDim.x + threadIdx.x;
    int n = M * 32;
    if (i < n) {
        int m = i >> 5;
        int t = i & 31;
        int b = t >> 3;
        int d = t & 7;
        int src_idx = (b * M + m) * 8 + d;   // [b][m][d] layout of c0 / out
        float val = c0[src_idx];
        v[i] = val;
        out[src_idx] = pc[0] * val;
        accz[i] = 0.0f;
    }
    if (i < E) {
        pair[i] = make_int2(src[i], dst[i]);
    }
}

// ---------------------------------------------------------------------------
// edge kernel: grid-stride over edges, one edge per warp per iteration,
// software-pipelined: next edge's (pair, ps, pd) prefetched one iteration
// ahead so the L2 gather chain is off the critical path.
//
// Per-edge math (identical to the proven R3 scheme):
//   lane t = b*8 + d.  XOR-permuted column regs: S[k] = Rs[k^d][d].
//   z[k] = S[k]*ps - D[k]*pd
//   keep-low butterfly (parallel): r = r[b][d] at lane (b,d)
//   allgather r_j = shfl_xor(r, j); cs = sum_j S[j]*r_j; cd = sum_j D[j]*r_j
//   acc[src][b][d] += cs ;  acc[dst][b][d] += -cd
// ---------------------------------------------------------------------------
__global__ void __launch_bounds__(EDGE_TPB)
edge_kernel(const float* __restrict__ v,
            const int2*  __restrict__ pair,
            const float* __restrict__ Rsrc,
            const float* __restrict__ Rdst,
            float*       __restrict__ acc,
            int E)
{
    const int t = threadIdx.x & 31;
    const int d = t & 7;
    const int warpsTotal = (EDGE_BLOCKS * EDGE_TPB) >> 5;
    const int w = (blockIdx.x * EDGE_TPB + threadIdx.x) >> 5;

    int e = w;
    if (e >= E) return;

    // prologue: fetch edge e's pair + vertex data
    int2 pr = __ldg(pair + e);
    float ps = __ldg(v + pr.x * 32 + t);
    float pd = __ldg(v + pr.y * 32 + t);

    const unsigned FULL = 0xffffffffu;

    for (; e < E; ) {
        int en = e + warpsTotal;
        int ep = (en < E) ? en : e;          // safe prefetch index
        // prefetch next iteration's chain NOW (consumed next iteration)
        int2 prn = __ldg(pair + ep);
        float psn = __ldg(v + prn.x * 32 + t);
        float pdn = __ldg(v + prn.y * 32 + t);

        // R loads for current edge (independent, fill the shadow)
        uintptr_t baseS = (uintptr_t)Rsrc + (size_t)e * 256 + (unsigned)(d * 36);
        uintptr_t baseD = (uintptr_t)Rdst + (size_t)e * 256 + (unsigned)(d * 36);

        float S[8], D[8];
#pragma unroll
        for (int k = 0; k < 8; k++) {
            S[k] = __ldg((const float*)(baseS ^ (uintptr_t)(k << 5)));
            D[k] = __ldg((const float*)(baseD ^ (uintptr_t)(k << 5)));
        }

        // z[k] = S[k]*ps - D[k]*pd : partial (this lane's d) of r[b][k^d]
        float z[8];
#pragma unroll
        for (int k = 0; k < 8; k++) {
            z[k] = fmaf(S[k], ps, -(D[k] * pd));
        }

        // keep-low butterfly, SEL-free thanks to XOR register layout.
#pragma unroll
        for (int k = 0; k < 4; k++) z[k] += __shfl_xor_sync(FULL, z[k + 4], 4);
#pragma unroll
        for (int k = 0; k < 2; k++) z[k] += __shfl_xor_sync(FULL, z[k + 2], 2);
        float r = z[0] + __shfl_xor_sync(FULL, z[1], 1);   // r[b][d]

        // allgather + transpose FMAs (shuffles shared by cs and cd)
        float cs = S[0] * r;
        float cd = D[0] * r;
#pragma unroll
        for (int j = 1; j < 8; j++) {
            float rj = __shfl_xor_sync(FULL, r, j);        // r[b][d^j]
            cs = fmaf(S[j], rj, cs);
            cd = fmaf(D[j], rj, cd);
        }

        atomicAdd(acc + pr.x * 32 + t, cs);
        atomicAdd(acc + pr.y * 32 + t, -cd);

        // rotate pipeline
        e = en;
        pr = prn;
        ps = psn;
        pd = pdn;
    }
}

// ---------------------------------------------------------------------------
// update: out[b][m][d] += pc[k] * acc[m][b][d]; optionally zero the other buffer
// ---------------------------------------------------------------------------
__global__ void update_kernel(const float* __restrict__ acc,
                              const float* __restrict__ pc,
                              int k,
                              float* __restrict__ out,
                              float* __restrict__ zother,
                              int M)
{
    int i = blockIdx.x * blockDim.x + threadIdx.x;
    int n = M * 32;
    if (i >= n) return;
    int m = i >> 5;
    int t = i & 31;
    int b = t >> 3;
    int d = t & 7;
    float val = acc[i];
    int oi = (b * M + m) * 8 + d;
    out[oi] += pc[k] * val;
    if (zother) zother[i] = 0.0f;
}

// ---------------------------------------------------------------------------
// launch  (7 launches total; ncu -s 5 captures launch #6 = 3rd edge_kernel)
// ---------------------------------------------------------------------------
extern "C" void kernel_launch(void* const* d_in, const int* in_sizes, int n_in,
                              void* d_out, int out_size)
{
    const float* c0  = (const float*)d_in[0];
    const int*   src = (const int*)  d_in[1];
    const int*   dst = (const int*)  d_in[2];
    const float* Rs  = (const float*)d_in[3];
    const float* Rd  = (const float*)d_in[4];
    const float* pc  = (const float*)d_in[5];
    float* out = (float*)d_out;

    int E = in_sizes[1];
    int M = in_sizes[0] / (B_CONST * D_CONST);

    float* bufA;  float* bufB;  int2* pairp;
    cudaGetSymbolAddress((void**)&bufA,  g_bufA);
    cudaGetSymbolAddress((void**)&bufB,  g_bufB);
    cudaGetSymbolAddress((void**)&pairp, g_pair);

    int nV = M * 32;
    int tb = 256;
    int nInit = (nV > E) ? nV : E;
    int gI = (nInit + tb - 1) / tb;
    int gV = (nV + tb - 1) / tb;

    init_kernel<<<gI, tb>>>(c0, src, dst, pc, out, bufA, bufB, pairp, M, E);

    // k = 1: B <- L(A); out += pc[1]*B; zero A
    edge_kernel<<<EDGE_BLOCKS, EDGE_TPB>>>(bufA, pairp, Rs, Rd, bufB, E);
    update_kernel<<<gV, tb>>>(bufB, pc, 1, out, bufA, M);

    // k = 2: A <- L(B); out += pc[2]*A; zero B
    edge_kernel<<<EDGE_BLOCKS, EDGE_TPB>>>(bufB, pairp, Rs, Rd, bufA, E);
    update_kernel<<<gV, tb>>>(bufA, pc, 2, out, bufB, M);

    // k = 3: B <- L(A); out += pc[3]*B
    edge_kernel<<<EDGE_BLOCKS, EDGE_TPB>>>(bufA, pairp, Rs, Rd, bufB, E);
    update_kernel<<<gV, tb>>>(bufB, pc, 3, out, nullptr, M);
}

// round 8
// speedup vs baseline: 1.3343x; 1.2787x over previous
#include <cuda_runtime.h>
#include <cuda_bf16.h>
#include <cstdint>

// Problem constants (SheafGluingPoly: B=4, M=50000, D=8, E=1600000, POLY_K=3, LAM=1)
#define B_CONST 4
#define D_CONST 8
#define MAX_MBD 1600000   // B*M*D
#define MAX_E   1600000

// Scratch: ping-pong vertex state in [m][d][b] layout (b fastest; 128B/vertex),
// plus packed (src,dst) pairs.
__device__ float g_bufA[MAX_MBD];
__device__ float g_bufB[MAX_MBD];
__device__ int2  g_pair[MAX_E];

__device__ __forceinline__ float4 shfl4(float4 a, int m, unsigned mask)
{
    float4 r;
    r.x = __shfl_xor_sync(mask, a.x, m);
    r.y = __shfl_xor_sync(mask, a.y, m);
    r.z = __shfl_xor_sync(mask, a.z, m);
    r.w = __shfl_xor_sync(mask, a.w, m);
    return r;
}
__device__ __forceinline__ void add4(float4& a, float4 b)
{
    a.x += b.x; a.y += b.y; a.z += b.z; a.w += b.w;
}
__device__ __forceinline__ void fma4(float4& acc, float s, float4 r)
{
    acc.x = fmaf(s, r.x, acc.x);
    acc.y = fmaf(s, r.y, acc.y);
    acc.z = fmaf(s, r.z, acc.z);
    acc.w = fmaf(s, r.w, acc.w);
}

// Vector float atomic reduction (sm_90+): one instruction, 16B.
__device__ __forceinline__ void red_add_v4(float* p, float4 v)
{
    asm volatile("red.global.add.v4.f32 [%0], {%1, %2, %3, %4};"
                 :: "l"(p), "f"(v.x), "f"(v.y), "f"(v.z), "f"(v.w)
                 : "memory");
}

// ---------------------------------------------------------------------------
// init (fused with pair packing):
//   v(A)[m][d][b] = c0[b][m][d], out = pc[0]*c0, acc(B) = 0, pair[e]=(src,dst)
// ---------------------------------------------------------------------------
__global__ void init_kernel(const float* __restrict__ c0,
                            const int*   __restrict__ src,
                            const int*   __restrict__ dst,
                            const float* __restrict__ pc,
                            float* __restrict__ out,
                            float* __restrict__ v,
                            float* __restrict__ accz,
                            int2*  __restrict__ pair,
                            int M, int E)
{
    int i = blockIdx.x * blockDim.x + threadIdx.x;
    int n = M * 32;
    if (i < n) {
        int m = i >> 5;
        int d = (i >> 2) & 7;
        int b = i & 3;
        int src_idx = (b * M + m) * 8 + d;   // [b][m][d] layout of c0 / out
        float val = c0[src_idx];
        v[i] = val;
        out[src_idx] = pc[0] * val;
        accz[i] = 0.0f;
    }
    if (i < E) {
        pair[i] = make_int2(src[i], dst[i]);
    }
}

// ---------------------------------------------------------------------------
// edge kernel: 4 edges per warp. lane t: g = t>>3 (edge-in-warp), d = t&7.
// Each lane carries all B=4 batches as float4 (v layout [m][d][b]).
//
// Register k holds column d of row rho(k,d) = ((k01 ^ d01) | k2*4):
//   offset = rho*32 + d*4 = (d*4 + (d&3)*32) ^ (k01*32) + k2*128
//   -> for fixed k the 8 lanes of a group touch ONE 128B line.
// Reduction over d (stage-4-first parallel order, per float4 component):
//   z[k] = S[k]*ps - D[k]*pd
//   stage4: z[k] += shfl_xor(z[k],4)   (rho invariant under d2; 8 indep)
//   stage2: z[k] += shfl_xor(z[k^2],2) for k in {0,1,4,5}
//   stage1: R0 = z[0]+shfl(z[1],1) = r[d01];  R1 = z[4]+shfl(z[5],1) = r[d01+4]
// Allgather r[(x^d01)|4h] = shfl_xor(Rh, x); transpose matvec local:
//   cs[d][:] = sum_k S[k]*r[rho(k,d)][:]  (float4 over b), cd analogous.
//   acc[src][d][:] += cs  (one red.v4);  acc[dst][d][:] += -cd.
// ---------------------------------------------------------------------------
__global__ void __launch_bounds__(256)
edge_kernel(const float* __restrict__ v,
            const int2*  __restrict__ pair,
            const float* __restrict__ Rsrc,
            const float* __restrict__ Rdst,
            float*       __restrict__ acc,
            int E)
{
    int tid = blockIdx.x * blockDim.x + threadIdx.x;
    int t = threadIdx.x & 31;
    int g = t >> 3;
    int d = t & 7;
    int e = (tid >> 5) * 4 + g;
    if (e >= E) return;

    const unsigned mask = 0xFFu << (t & 24);   // this 8-lane group

    int2 pr = __ldg(pair + e);

    float4 ps = *(const float4*)(v + pr.x * 32 + d * 4);
    float4 pd = *(const float4*)(v + pr.y * 32 + d * 4);

    const char* SB = (const char*)Rsrc + (size_t)e * 256;
    const char* DB = (const char*)Rdst + (size_t)e * 256;
    unsigned cbase = (unsigned)(d * 4 + ((d & 3) << 5));

    float S[8], D[8];
#pragma unroll
    for (int x = 0; x < 4; x++) {
        unsigned c = cbase ^ (unsigned)(x << 5);
        S[x]     = *(const float*)(SB + c);         // row (x^d01)    , col d
        S[x + 4] = *(const float*)(SB + c + 128);   // row (x^d01)+4  , col d
        D[x]     = *(const float*)(DB + c);
        D[x + 4] = *(const float*)(DB + c + 128);
    }

    // forward partials: z[k][b] = S[k]*ps[b] - D[k]*pd[b]
    float4 z[8];
#pragma unroll
    for (int k = 0; k < 8; k++) {
        z[k].x = fmaf(S[k], ps.x, -(D[k] * pd.x));
        z[k].y = fmaf(S[k], ps.y, -(D[k] * pd.y));
        z[k].z = fmaf(S[k], ps.z, -(D[k] * pd.z));
        z[k].w = fmaf(S[k], ps.w, -(D[k] * pd.w));
    }

    // stage 4: 8 independent self-exchanges
#pragma unroll
    for (int k = 0; k < 8; k++) add4(z[k], shfl4(z[k], 4, mask));
    // stage 2: 4 independent
    add4(z[0], shfl4(z[2], 2, mask));
    add4(z[1], shfl4(z[3], 2, mask));
    add4(z[4], shfl4(z[6], 2, mask));
    add4(z[5], shfl4(z[7], 2, mask));
    // stage 1: 2 independent
    float4 R0 = z[0]; add4(R0, shfl4(z[1], 1, mask));   // r[d01][:]
    float4 R1 = z[4]; add4(R1, shfl4(z[5], 1, mask));   // r[d01+4][:]

    // allgather + transpose matvec (local FMAs)
    float4 cs = make_float4(0.f, 0.f, 0.f, 0.f);
    float4 cd = make_float4(0.f, 0.f, 0.f, 0.f);
    fma4(cs, S[0], R0);  fma4(cs, S[4], R1);
    fma4(cd, D[0], R0);  fma4(cd, D[4], R1);
#pragma unroll
    for (int x = 1; x < 4; x++) {
        float4 r0x = shfl4(R0, x, mask);   // r[x^d01][:]
        float4 r1x = shfl4(R1, x, mask);   // r[(x^d01)+4][:]
        fma4(cs, S[x],     r0x);
        fma4(cd, D[x],     r0x);
        fma4(cs, S[x + 4], r1x);
        fma4(cd, D[x + 4], r1x);
    }

    red_add_v4(acc + pr.x * 32 + d * 4, cs);
    red_add_v4(acc + pr.y * 32 + d * 4,
               make_float4(-cd.x, -cd.y, -cd.z, -cd.w));
}

// ---------------------------------------------------------------------------
// update: out[b][m][d] += pc[k] * acc[m][d][b]; optionally zero other buffer
// ---------------------------------------------------------------------------
__global__ void update_kernel(const float* __restrict__ acc,
                              const float* __restrict__ pc,
                              int k,
                              float* __restrict__ out,
                              float* __restrict__ zother,
                              int M)
{
    int i = blockIdx.x * blockDim.x + threadIdx.x;
    int n = M * 32;
    if (i >= n) return;
    int m = i >> 5;
    int d = (i >> 2) & 7;
    int b = i & 3;
    float val = acc[i];
    int oi = (b * M + m) * 8 + d;
    out[oi] += pc[k] * val;
    if (zother) zother[i] = 0.0f;
}

// ---------------------------------------------------------------------------
// launch  (7 launches total; ncu -s 5 captures launch #6 = 3rd edge_kernel)
// ---------------------------------------------------------------------------
extern "C" void kernel_launch(void* const* d_in, const int* in_sizes, int n_in,
                              void* d_out, int out_size)
{
    const float* c0  = (const float*)d_in[0];
    const int*   src = (const int*)  d_in[1];
    const int*   dst = (const int*)  d_in[2];
    const float* Rs  = (const float*)d_in[3];
    const float* Rd  = (const float*)d_in[4];
    const float* pc  = (const float*)d_in[5];
    float* out = (float*)d_out;

    int E = in_sizes[1];
    int M = in_sizes[0] / (B_CONST * D_CONST);

    float* bufA;  float* bufB;  int2* pairp;
    cudaGetSymbolAddress((void**)&bufA,  g_bufA);
    cudaGetSymbolAddress((void**)&bufB,  g_bufB);
    cudaGetSymbolAddress((void**)&pairp, g_pair);

    int nV = M * 32;
    int tb = 256;
    int nInit = (nV > E) ? nV : E;
    int gI = (nInit + tb - 1) / tb;
    int gV = (nV + tb - 1) / tb;
    // 4 edges per warp -> 8 lanes per edge
    int gE = (E * 8 + tb - 1) / tb;

    init_kernel<<<gI, tb>>>(c0, src, dst, pc, out, bufA, bufB, pairp, M, E);

    // k = 1: B <- L(A); out += pc[1]*B; zero A
    edge_kernel<<<gE, tb>>>(bufA, pairp, Rs, Rd, bufB, E);
    update_kernel<<<gV, tb>>>(bufB, pc, 1, out, bufA, M);

    // k = 2: A <- L(B); out += pc[2]*A; zero B
    edge_kernel<<<gE, tb>>>(bufB, pairp, Rs, Rd, bufA, E);
    update_kernel<<<gV, tb>>>(bufA, pc, 2, out, bufB, M);

    // k = 3: B <- L(A); out += pc[3]*B
    edge_kernel<<<gE, tb>>>(bufA, pairp, Rs, Rd, bufB, E);
    update_kernel<<<gV, tb>>>(bufB, pc, 3, out, nullptr, M);
}

// round 9
// speedup vs baseline: 1.4396x; 1.0789x over previous
#include <cuda_runtime.h>
#include <cuda_bf16.h>
#include <cstdint>

// Problem constants (SheafGluingPoly: B=4, M=50000, D=8, E=1600000, POLY_K=3, LAM=1)
#define B_CONST 4
#define D_CONST 8
#define MAX_MBD 1600000   // B*M*D
#define MAX_E   1600000

// Scratch: ping-pong vertex state in [m][d][b] layout (b fastest; 128B/vertex),
// plus packed (src,dst) pairs.
__device__ float g_bufA[MAX_MBD];
__device__ float g_bufB[MAX_MBD];
__device__ int2  g_pair[MAX_E];

__device__ __forceinline__ float4 shfl4(float4 a, int m, unsigned mask)
{
    float4 r;
    r.x = __shfl_xor_sync(mask, a.x, m);
    r.y = __shfl_xor_sync(mask, a.y, m);
    r.z = __shfl_xor_sync(mask, a.z, m);
    r.w = __shfl_xor_sync(mask, a.w, m);
    return r;
}
__device__ __forceinline__ void add4(float4& a, float4 b)
{
    a.x += b.x; a.y += b.y; a.z += b.z; a.w += b.w;
}
__device__ __forceinline__ void fma4(float4& acc, float s, float4 r)
{
    acc.x = fmaf(s, r.x, acc.x);
    acc.y = fmaf(s, r.y, acc.y);
    acc.z = fmaf(s, r.z, acc.z);
    acc.w = fmaf(s, r.w, acc.w);
}

// Vector float atomic reduction (sm_90+): one instruction, 16B.
__device__ __forceinline__ void red_add_v4(float* p, float4 v)
{
    asm volatile("red.global.add.v4.f32 [%0], {%1, %2, %3, %4};"
                 :: "l"(p), "f"(v.x), "f"(v.y), "f"(v.z), "f"(v.w)
                 : "memory");
}

// ---------------------------------------------------------------------------
// init (fused with pair packing):
//   v(A)[m][d][b] = c0[b][m][d], out = pc[0]*c0, acc(B) = 0, pair[e]=(src,dst)
// ---------------------------------------------------------------------------
__global__ void init_kernel(const float* __restrict__ c0,
                            const int*   __restrict__ src,
                            const int*   __restrict__ dst,
                            const float* __restrict__ pc,
                            float* __restrict__ out,
                            float* __restrict__ v,
                            float* __restrict__ accz,
                            int2*  __restrict__ pair,
                            int M, int E)
{
    int i = blockIdx.x * blockDim.x + threadIdx.x;
    int n = M * 32;
    if (i < n) {
        int m = i >> 5;
        int d = (i >> 2) & 7;
        int b = i & 3;
        int src_idx = (b * M + m) * 8 + d;   // [b][m][d] layout of c0 / out
        float val = c0[src_idx];
        v[i] = val;
        out[src_idx] = pc[0] * val;
        accz[i] = 0.0f;
    }
    if (i < E) {
        pair[i] = make_int2(src[i], dst[i]);
    }
}

// ---------------------------------------------------------------------------
// edge kernel: 4 edges per warp. lane t: g = t>>3 (edge-in-warp), d = t&7.
// Each lane carries all B=4 batches as float4 (v layout [m][d][b]).
//
// Register k holds column d of row rho(k,d) = ((k01 ^ d01) | k2*4):
//   offset = (d*4 + (d&3)*32) ^ (k01*32) + k2*128
//   -> for fixed k the 8 lanes of a group touch ONE 128B line.
// Reduction over d — keep-low butterfly (8 exchange shfl4 total; float4
// components give ILP=4 so the 3-deep chain is latency-tolerant):
//   z[k] = S[k]*ps - D[k]*pd
//   stage1: z[k] += shfl_xor(z[k^1],1), k in {0,2,4,6}
//   stage2: z[k] += shfl_xor(z[k^2],2), k in {0,4}
//   stage4: R0 = z[0]+shfl(z[0],4) = r[d01];  R1 = z[4]+shfl(z[4],4) = r[d01+4]
// Allgather r[(x^d01)|4h] = shfl_xor(Rh, x) (6 shfl4); transpose local:
//   cs[d][:] = sum_k S[k]*r[rho(k,d)][:]  (float4 over b), cd analogous.
//   acc[src][d][:] += cs  (one red.v4);  acc[dst][d][:] += -cd.
// ---------------------------------------------------------------------------
__global__ void __launch_bounds__(256)
edge_kernel(const float* __restrict__ v,
            const int2*  __restrict__ pair,
            const float* __restrict__ Rsrc,
            const float* __restrict__ Rdst,
            float*       __restrict__ acc,
            int E)
{
    int tid = blockIdx.x * blockDim.x + threadIdx.x;
    int t = threadIdx.x & 31;
    int g = t >> 3;
    int d = t & 7;
    int e = (tid >> 5) * 4 + g;
    if (e >= E) return;

    const unsigned mask = 0xFFu << (t & 24);   // this 8-lane group

    int2 pr = __ldg(pair + e);

    float4 ps = *(const float4*)(v + pr.x * 32 + d * 4);
    float4 pd = *(const float4*)(v + pr.y * 32 + d * 4);

    const char* SB = (const char*)Rsrc + (size_t)e * 256;
    const char* DB = (const char*)Rdst + (size_t)e * 256;
    unsigned cbase = (unsigned)(d * 4 + ((d & 3) << 5));

    float S[8], D[8];
#pragma unroll
    for (int x = 0; x < 4; x++) {
        unsigned c = cbase ^ (unsigned)(x << 5);
        S[x]     = *(const float*)(SB + c);         // row (x^d01)    , col d
        S[x + 4] = *(const float*)(SB + c + 128);   // row (x^d01)+4  , col d
        D[x]     = *(const float*)(DB + c);
        D[x + 4] = *(const float*)(DB + c + 128);
    }

    // forward partials: z[k][b] = S[k]*ps[b] - D[k]*pd[b]
    float4 z[8];
#pragma unroll
    for (int k = 0; k < 8; k++) {
        z[k].x = fmaf(S[k], ps.x, -(D[k] * pd.x));
        z[k].y = fmaf(S[k], ps.y, -(D[k] * pd.y));
        z[k].z = fmaf(S[k], ps.z, -(D[k] * pd.z));
        z[k].w = fmaf(S[k], ps.w, -(D[k] * pd.w));
    }

    // keep-low butterfly (valid for rho layout; verified in R5):
    // stage 1: 4 independent exchanges
    add4(z[0], shfl4(z[1], 1, mask));
    add4(z[2], shfl4(z[3], 1, mask));
    add4(z[4], shfl4(z[5], 1, mask));
    add4(z[6], shfl4(z[7], 1, mask));
    // stage 2: 2 independent
    add4(z[0], shfl4(z[2], 2, mask));
    add4(z[4], shfl4(z[6], 2, mask));
    // stage 4: 2 self-exchanges (rho invariant under d2)
    float4 R0 = z[0]; add4(R0, shfl4(z[0], 4, mask));   // r[d01][:]
    float4 R1 = z[4]; add4(R1, shfl4(z[4], 4, mask));   // r[d01+4][:]

    // allgather + transpose matvec (local FMAs)
    float4 cs = make_float4(0.f, 0.f, 0.f, 0.f);
    float4 cd = make_float4(0.f, 0.f, 0.f, 0.f);
    fma4(cs, S[0], R0);  fma4(cs, S[4], R1);
    fma4(cd, D[0], R0);  fma4(cd, D[4], R1);
#pragma unroll
    for (int x = 1; x < 4; x++) {
        float4 r0x = shfl4(R0, x, mask);   // r[x^d01][:]
        float4 r1x = shfl4(R1, x, mask);   // r[(x^d01)+4][:]
        fma4(cs, S[x],     r0x);
        fma4(cd, D[x],     r0x);
        fma4(cs, S[x + 4], r1x);
        fma4(cd, D[x + 4], r1x);
    }

    red_add_v4(acc + pr.x * 32 + d * 4, cs);
    red_add_v4(acc + pr.y * 32 + d * 4,
               make_float4(-cd.x, -cd.y, -cd.z, -cd.w));
}

// ---------------------------------------------------------------------------
// update: out[b][m][d] += pc[k] * acc[m][d][b]; optionally zero other buffer
// ---------------------------------------------------------------------------
__global__ void update_kernel(const float* __restrict__ acc,
                              const float* __restrict__ pc,
                              int k,
                              float* __restrict__ out,
                              float* __restrict__ zother,
                              int M)
{
    int i = blockIdx.x * blockDim.x + threadIdx.x;
    int n = M * 32;
    if (i >= n) return;
    int m = i >> 5;
    int d = (i >> 2) & 7;
    int b = i & 3;
    float val = acc[i];
    int oi = (b * M + m) * 8 + d;
    out[oi] += pc[k] * val;
    if (zother) zother[i] = 0.0f;
}

// ---------------------------------------------------------------------------
// launch  (7 launches total; ncu -s 5 captures launch #6 = 3rd edge_kernel)
// ---------------------------------------------------------------------------
extern "C" void kernel_launch(void* const* d_in, const int* in_sizes, int n_in,
                              void* d_out, int out_size)
{
    const float* c0  = (const float*)d_in[0];
    const int*   src = (const int*)  d_in[1];
    const int*   dst = (const int*)  d_in[2];
    const float* Rs  = (const float*)d_in[3];
    const float* Rd  = (const float*)d_in[4];
    const float* pc  = (const float*)d_in[5];
    float* out = (float*)d_out;

    int E = in_sizes[1];
    int M = in_sizes[0] / (B_CONST * D_CONST);

    float* bufA;  float* bufB;  int2* pairp;
    cudaGetSymbolAddress((void**)&bufA,  g_bufA);
    cudaGetSymbolAddress((void**)&bufB,  g_bufB);
    cudaGetSymbolAddress((void**)&pairp, g_pair);

    int nV = M * 32;
    int tb = 256;
    int nInit = (nV > E) ? nV : E;
    int gI = (nInit + tb - 1) / tb;
    int gV = (nV + tb - 1) / tb;
    // 4 edges per warp -> 8 lanes per edge
    int gE = (E * 8 + tb - 1) / tb;

    init_kernel<<<gI, tb>>>(c0, src, dst, pc, out, bufA, bufB, pairp, M, E);

    // k = 1: B <- L(A); out += pc[1]*B; zero A
    edge_kernel<<<gE, tb>>>(bufA, pairp, Rs, Rd, bufB, E);
    update_kernel<<<gV, tb>>>(bufB, pc, 1, out, bufA, M);

    // k = 2: A <- L(B); out += pc[2]*A; zero B
    edge_kernel<<<gE, tb>>>(bufB, pairp, Rs, Rd, bufA, E);
    update_kernel<<<gV, tb>>>(bufA, pc, 2, out, bufB, M);

    // k = 3: B <- L(A); out += pc[3]*B
    edge_kernel<<<gE, tb>>>(bufA, pairp, Rs, Rd, bufB, E);
    update_kernel<<<gV, tb>>>(bufB, pc, 3, out, nullptr, M);
}

// round 10
// speedup vs baseline: 1.4639x; 1.0169x over previous
#include <cuda_runtime.h>
#include <cuda_bf16.h>
#include <cstdint>

// Problem constants (SheafGluingPoly: B=4, M=50000, D=8, E=1600000, POLY_K=3, LAM=1)
#define B_CONST 4
#define D_CONST 8
#define MAX_MBD 1600000   // B*M*D
#define MAX_E   1600000

// Scratch: ping-pong vertex state in [m][d][b] layout (b fastest; 128B/vertex),
// plus packed (src,dst) pairs.
__device__ float g_bufA[MAX_MBD];
__device__ float g_bufB[MAX_MBD];
__device__ int2  g_pair[MAX_E];

__device__ __forceinline__ float4 shfl4(float4 a, int m, unsigned mask)
{
    float4 r;
    r.x = __shfl_xor_sync(mask, a.x, m);
    r.y = __shfl_xor_sync(mask, a.y, m);
    r.z = __shfl_xor_sync(mask, a.z, m);
    r.w = __shfl_xor_sync(mask, a.w, m);
    return r;
}
__device__ __forceinline__ void add4(float4& a, float4 b)
{
    a.x += b.x; a.y += b.y; a.z += b.z; a.w += b.w;
}
__device__ __forceinline__ void fma4(float4& acc, float s, float4 r)
{
    acc.x = fmaf(s, r.x, acc.x);
    acc.y = fmaf(s, r.y, acc.y);
    acc.z = fmaf(s, r.z, acc.z);
    acc.w = fmaf(s, r.w, acc.w);
}

// Vector float atomic reduction (sm_90+): one instruction, 16B.
__device__ __forceinline__ void red_add_v4(float* p, float4 v)
{
    asm volatile("red.global.add.v4.f32 [%0], {%1, %2, %3, %4};"
                 :: "l"(p), "f"(v.x), "f"(v.y), "f"(v.z), "f"(v.w)
                 : "memory");
}

// Block-swizzled smem byte address: XOR bits 5-7 with the 256B-block id.
// Keeps every access inside its 256B block; makes the 4 groups' LDS bank
// sets disjoint -> conflict-free column reads.
__device__ __forceinline__ unsigned sw_addr(unsigned a)
{
    return a ^ (((a >> 8) & 7u) << 5);
}

// ---------------------------------------------------------------------------
// init (fused with pair packing):
//   v(A)[m][d][b] = c0[b][m][d], out = pc[0]*c0, acc(B) = 0, pair[e]=(src,dst)
// ---------------------------------------------------------------------------
__global__ void init_kernel(const float* __restrict__ c0,
                            const int*   __restrict__ src,
                            const int*   __restrict__ dst,
                            const float* __restrict__ pc,
                            float* __restrict__ out,
                            float* __restrict__ v,
                            float* __restrict__ accz,
                            int2*  __restrict__ pair,
                            int M, int E)
{
    int i = blockIdx.x * blockDim.x + threadIdx.x;
    int n = M * 32;
    if (i < n) {
        int m = i >> 5;
        int d = (i >> 2) & 7;
        int b = i & 3;
        int src_idx = (b * M + m) * 8 + d;   // [b][m][d] layout of c0 / out
        float val = c0[src_idx];
        v[i] = val;
        out[src_idx] = pc[0] * val;
        accz[i] = 0.0f;
    }
    if (i < E) {
        pair[i] = make_int2(src[i], dst[i]);
    }
}

// ---------------------------------------------------------------------------
// edge kernel: 4 edges per warp. lane t: g = t>>3 (edge-in-warp), d = t&7.
// Each lane carries all B=4 batches as float4 (v layout [m][d][b]).
//
// R load path: the warp's 4 edges are contiguous -> Rs block (1KB) and Rd
// block (1KB) loaded with 4 coalesced LDG.128 (16 wavefronts, the data floor),
// staged through swizzled smem, then read back as ρ-layout columns with 16
// conflict-free scalar LDS.
//
// Register k holds column d of row rho(k,d) = ((k01 ^ d01) | 4*k2).
// Reduction over d — keep-low butterfly (float4 ILP hides the 3-deep chain):
//   z[k] = S[k]*ps - D[k]*pd
//   stage1: z[k] += shfl_xor(z[k^1],1), k in {0,2,4,6}
//   stage2: z[k] += shfl_xor(z[k^2],2), k in {0,4}
//   stage4: R0 = z[0]+shfl(z[0],4) = r[d01];  R1 = z[4]+shfl(z[4],4) = r[d01+4]
// Allgather r[(x^d01)|4h] = shfl_xor(Rh, x) (6 shfl4); transpose local:
//   cs[d][:] = sum_k S[k]*r[rho(k,d)][:]  (float4 over b), cd analogous.
//   acc[src][d][:] += cs  (one red.v4);  acc[dst][d][:] += -cd.
// ---------------------------------------------------------------------------
__global__ void __launch_bounds__(256)
edge_kernel(const float* __restrict__ v,
            const int2*  __restrict__ pair,
            const float* __restrict__ Rsrc,
            const float* __restrict__ Rdst,
            float*       __restrict__ acc,
            int E)
{
    __shared__ float smem[8 * 512];   // 2KB per warp, 8 warps

    int tid = blockIdx.x * blockDim.x + threadIdx.x;
    int t = threadIdx.x & 31;
    int g = t >> 3;
    int d = t & 7;
    int warpG = tid >> 5;
    int e = warpG * 4 + g;

    char* ws = (char*)(smem + (threadIdx.x >> 5) * 512);

    // ---- coalesced R load (4 edges x 512B) + swizzled smem stage ----
    {
        size_t fbase = (size_t)warpG * 256;           // floats: 4 edges * 64
        size_t flimit = (size_t)E * 64;
        const float4* gS = (const float4*)(Rsrc + fbase);
        const float4* gD = (const float4*)(Rdst + fbase);
        unsigned a0 = (unsigned)t * 16;               // byte offset of chunk 0
        unsigned a1 = a0 + 512;                       // byte offset of chunk 1
        if (fbase + (size_t)t * 4 + 4 <= flimit) {
            float4 s0 = __ldg(gS + t);
            float4 d0 = __ldg(gD + t);
            *(float4*)(ws + sw_addr(a0))        = s0;
            *(float4*)(ws + sw_addr(a0 + 1024)) = d0;
        }
        if (fbase + 128 + (size_t)t * 4 + 4 <= flimit) {
            float4 s1 = __ldg(gS + 32 + t);
            float4 d1 = __ldg(gD + 32 + t);
            *(float4*)(ws + sw_addr(a1))        = s1;
            *(float4*)(ws + sw_addr(a1 + 1024)) = d1;
        }
    }
    __syncwarp();

    if (e >= E) return;

    const unsigned mask = 0xFFu << (t & 24);   // this 8-lane group

    int2 pr = __ldg(pair + e);

    float4 ps = *(const float4*)(v + pr.x * 32 + d * 4);
    float4 pd = *(const float4*)(v + pr.y * 32 + d * 4);

    // ---- conflict-free ρ-layout column reads from smem ----
    // Rs[row][d] of edge g lives at ws byte: g*256 + ((row^g)<<5) + d*4
    // Rd[row][d]                      at: 1024 + g*256 + ((row^g^4)<<5) + d*4
    float S[8], D[8];
    {
        unsigned q = (unsigned)((d & 3) ^ g);
        unsigned AS = (unsigned)(g * 256 + d * 4) + (q << 5);
        unsigned AD = AS + 1024u;   // note: rho^g^4 toggles the +128 pairing
#pragma unroll
        for (int k = 0; k < 8; k++) {
            // rho(k,d)^g = ((k&3)^q) | (k&4); bits disjoint -> OR == ADD
            unsigned xs = ((unsigned)(k & 3) << 5);
            unsigned hiS = (k & 4) ? 128u : 0u;
            unsigned hiD = (k & 4) ? 0u : 128u;   // ^4 flips row bit 2
            S[k] = *(const float*)(ws + ((AS ^ xs) + hiS));
            D[k] = *(const float*)(ws + ((AD ^ xs) + hiD));
        }
    }

    // forward partials: z[k][b] = S[k]*ps[b] - D[k]*pd[b]
    float4 z[8];
#pragma unroll
    for (int k = 0; k < 8; k++) {
        z[k].x = fmaf(S[k], ps.x, -(D[k] * pd.x));
        z[k].y = fmaf(S[k], ps.y, -(D[k] * pd.y));
        z[k].z = fmaf(S[k], ps.z, -(D[k] * pd.z));
        z[k].w = fmaf(S[k], ps.w, -(D[k] * pd.w));
    }

    // keep-low butterfly (validated in R5/R9):
    add4(z[0], shfl4(z[1], 1, mask));
    add4(z[2], shfl4(z[3], 1, mask));
    add4(z[4], shfl4(z[5], 1, mask));
    add4(z[6], shfl4(z[7], 1, mask));
    add4(z[0], shfl4(z[2], 2, mask));
    add4(z[4], shfl4(z[6], 2, mask));
    float4 R0 = z[0]; add4(R0, shfl4(z[0], 4, mask));   // r[d01][:]
    float4 R1 = z[4]; add4(R1, shfl4(z[4], 4, mask));   // r[d01+4][:]

    // allgather + transpose matvec (local FMAs)
    float4 cs = make_float4(0.f, 0.f, 0.f, 0.f);
    float4 cd = make_float4(0.f, 0.f, 0.f, 0.f);
    fma4(cs, S[0], R0);  fma4(cs, S[4], R1);
    fma4(cd, D[0], R0);  fma4(cd, D[4], R1);
#pragma unroll
    for (int x = 1; x < 4; x++) {
        float4 r0x = shfl4(R0, x, mask);   // r[x^d01][:]
        float4 r1x = shfl4(R1, x, mask);   // r[(x^d01)+4][:]
        fma4(cs, S[x],     r0x);
        fma4(cd, D[x],     r0x);
        fma4(cs, S[x + 4], r1x);
        fma4(cd, D[x + 4], r1x);
    }

    red_add_v4(acc + pr.x * 32 + d * 4, cs);
    red_add_v4(acc + pr.y * 32 + d * 4,
               make_float4(-cd.x, -cd.y, -cd.z, -cd.w));
}

// ---------------------------------------------------------------------------
// update: out[b][m][d] += pc[k] * acc[m][d][b]; optionally zero other buffer
// ---------------------------------------------------------------------------
__global__ void update_kernel(const float* __restrict__ acc,
                              const float* __restrict__ pc,
                              int k,
                              float* __restrict__ out,
                              float* __restrict__ zother,
                              int M)
{
    int i = blockIdx.x * blockDim.x + threadIdx.x;
    int n = M * 32;
    if (i >= n) return;
    int m = i >> 5;
    int d = (i >> 2) & 7;
    int b = i & 3;
    float val = acc[i];
    int oi = (b * M + m) * 8 + d;
    out[oi] += pc[k] * val;
    if (zother) zother[i] = 0.0f;
}

// ---------------------------------------------------------------------------
// launch  (7 launches total; ncu -s 5 captures launch #6 = 3rd edge_kernel)
// ---------------------------------------------------------------------------
extern "C" void kernel_launch(void* const* d_in, const int* in_sizes, int n_in,
                              void* d_out, int out_size)
{
    const float* c0  = (const float*)d_in[0];
    const int*   src = (const int*)  d_in[1];
    const int*   dst = (const int*)  d_in[2];
    const float* Rs  = (const float*)d_in[3];
    const float* Rd  = (const float*)d_in[4];
    const float* pc  = (const float*)d_in[5];
    float* out = (float*)d_out;

    int E = in_sizes[1];
    int M = in_sizes[0] / (B_CONST * D_CONST);

    float* bufA;  float* bufB;  int2* pairp;
    cudaGetSymbolAddress((void**)&bufA,  g_bufA);
    cudaGetSymbolAddress((void**)&bufB,  g_bufB);
    cudaGetSymbolAddress((void**)&pairp, g_pair);

    int nV = M * 32;
    int tb = 256;
    int nInit = (nV > E) ? nV : E;
    int gI = (nInit + tb - 1) / tb;
    int gV = (nV + tb - 1) / tb;
    // 4 edges per warp = 32 edges per 256-thread block
    int gE = (E + 31) / 32;

    init_kernel<<<gI, tb>>>(c0, src, dst, pc, out, bufA, bufB, pairp, M, E);

    // k = 1: B <- L(A); out += pc[1]*B; zero A
    edge_kernel<<<gE, tb>>>(bufA, pairp, Rs, Rd, bufB, E);
    update_kernel<<<gV, tb>>>(bufB, pc, 1, out, bufA, M);

    // k = 2: A <- L(B); out += pc[2]*A; zero B
    edge_kernel<<<gE, tb>>>(bufB, pairp, Rs, Rd, bufA, E);
    update_kernel<<<gV, tb>>>(bufA, pc, 2, out, bufB, M);

    // k = 3: B <- L(A); out += pc[3]*B
    edge_kernel<<<gE, tb>>>(bufA, pairp, Rs, Rd, bufB, E);
    update_kernel<<<gV, tb>>>(bufB, pc, 3, out, nullptr, M);
}

// round 11
// speedup vs baseline: 1.5705x; 1.0728x over previous
#include <cuda_runtime.h>
#include <cuda_bf16.h>
#include <cstdint>

// Problem constants (SheafGluingPoly: B=4, M=50000, D=8, E=1600000, POLY_K=3, LAM=1)
#define B_CONST 4
#define D_CONST 8
#define MAX_MBD 1600000   // B*M*D
#define MAX_E   1600000

// Scratch: ping-pong vertex state in [m][d][b] layout (b fastest; 128B/vertex),
// plus packed (src,dst) pairs.
__device__ float g_bufA[MAX_MBD];
__device__ float g_bufB[MAX_MBD];
__device__ int2  g_pair[MAX_E];

__device__ __forceinline__ float4 shfl4(float4 a, int m, unsigned mask)
{
    float4 r;
    r.x = __shfl_xor_sync(mask, a.x, m);
    r.y = __shfl_xor_sync(mask, a.y, m);
    r.z = __shfl_xor_sync(mask, a.z, m);
    r.w = __shfl_xor_sync(mask, a.w, m);
    return r;
}
__device__ __forceinline__ void add4(float4& a, float4 b)
{
    a.x += b.x; a.y += b.y; a.z += b.z; a.w += b.w;
}
__device__ __forceinline__ void fma4(float4& acc, float s, float4 r)
{
    acc.x = fmaf(s, r.x, acc.x);
    acc.y = fmaf(s, r.y, acc.y);
    acc.z = fmaf(s, r.z, acc.z);
    acc.w = fmaf(s, r.w, acc.w);
}
// z[k] = S*ps - D*pd (componentwise)
__device__ __forceinline__ float4 zmk(float S, float D, float4 ps, float4 pd)
{
    float4 z;
    z.x = fmaf(S, ps.x, -(D * pd.x));
    z.y = fmaf(S, ps.y, -(D * pd.y));
    z.z = fmaf(S, ps.z, -(D * pd.z));
    z.w = fmaf(S, ps.w, -(D * pd.w));
    return z;
}

// Vector float atomic reduction (sm_90+): one instruction, 16B.
__device__ __forceinline__ void red_add_v4(float* p, float4 v)
{
    asm volatile("red.global.add.v4.f32 [%0], {%1, %2, %3, %4};"
                 :: "l"(p), "f"(v.x), "f"(v.y), "f"(v.z), "f"(v.w)
                 : "memory");
}

// Block-swizzled smem byte address: XOR bits 5-7 with the 256B-block id.
__device__ __forceinline__ unsigned sw_addr(unsigned a)
{
    return a ^ (((a >> 8) & 7u) << 5);
}

// ---------------------------------------------------------------------------
// init (fused with pair packing):
//   v(A)[m][d][b] = c0[b][m][d], out = pc[0]*c0, acc(B) = 0, pair[e]=(src,dst)
// ---------------------------------------------------------------------------
__global__ void init_kernel(const float* __restrict__ c0,
                            const int*   __restrict__ src,
                            const int*   __restrict__ dst,
                            const float* __restrict__ pc,
                            float* __restrict__ out,
                            float* __restrict__ v,
                            float* __restrict__ accz,
                            int2*  __restrict__ pair,
                            int M, int E)
{
    int i = blockIdx.x * blockDim.x + threadIdx.x;
    int n = M * 32;
    if (i < n) {
        int m = i >> 5;
        int d = (i >> 2) & 7;
        int b = i & 3;
        int src_idx = (b * M + m) * 8 + d;   // [b][m][d] layout of c0 / out
        float val = c0[src_idx];
        v[i] = val;
        out[src_idx] = pc[0] * val;
        accz[i] = 0.0f;
    }
    if (i < E) {
        pair[i] = make_int2(src[i], dst[i]);
    }
}

// ---------------------------------------------------------------------------
// edge kernel: 4 edges per warp. lane t: g = t>>3 (edge-in-warp), d = t&7.
// Each lane carries all B=4 batches as float4 (v layout [m][d][b]).
//
// R load path: warp's 4 contiguous edges -> 4 coalesced LDG.128 (data floor),
// staged through swizzled smem, read back as ρ-layout columns (16 LDS,
// conflict-free).
//
// Register k holds column d of row rho(k,d) = ((k01 ^ d01) | 4*k2).
// FUSED keep-low butterfly: each (z[2k], z[2k+1]) pair is exchanged and
// folded immediately after production -> peak z live = ~5 float4 (was 8),
// cutting register pressure so 5 blocks/SM fit (launch_bounds(256,5)).
//   stage2: z[0]+=shfl(z[2],2); z[4]+=shfl(z[6],2)
//   stage4: R0 = z[0]+shfl(z[0],4) = r[d01];  R1 = z[4]+shfl(z[4],4)
// Allgather (6 shfl4) + local transpose matvec; one red.v4 per vertex side.
// ---------------------------------------------------------------------------
__global__ void __launch_bounds__(256, 5)
edge_kernel(const float* __restrict__ v,
            const int2*  __restrict__ pair,
            const float* __restrict__ Rsrc,
            const float* __restrict__ Rdst,
            float*       __restrict__ acc,
            int E)
{
    __shared__ float smem[8 * 512];   // 2KB per warp, 8 warps

    int tid = blockIdx.x * blockDim.x + threadIdx.x;
    int t = threadIdx.x & 31;
    int g = t >> 3;
    int d = t & 7;
    int warpG = tid >> 5;
    int e = warpG * 4 + g;

    char* ws = (char*)(smem + (threadIdx.x >> 5) * 512);

    // ---- coalesced R load (4 edges x 512B) + swizzled smem stage ----
    {
        size_t fbase = (size_t)warpG * 256;           // floats: 4 edges * 64
        size_t flimit = (size_t)E * 64;
        const float4* gS = (const float4*)(Rsrc + fbase);
        const float4* gD = (const float4*)(Rdst + fbase);
        unsigned a0 = (unsigned)t * 16;               // byte offset of chunk 0
        unsigned a1 = a0 + 512;                       // byte offset of chunk 1
        if (fbase + (size_t)t * 4 + 4 <= flimit) {
            float4 s0 = __ldg(gS + t);
            float4 d0 = __ldg(gD + t);
            *(float4*)(ws + sw_addr(a0))        = s0;
            *(float4*)(ws + sw_addr(a0 + 1024)) = d0;
        }
        if (fbase + 128 + (size_t)t * 4 + 4 <= flimit) {
            float4 s1 = __ldg(gS + 32 + t);
            float4 d1 = __ldg(gD + 32 + t);
            *(float4*)(ws + sw_addr(a1))        = s1;
            *(float4*)(ws + sw_addr(a1 + 1024)) = d1;
        }
    }
    __syncwarp();

    if (e >= E) return;

    const unsigned mask = 0xFFu << (t & 24);   // this 8-lane group

    int2 pr = __ldg(pair + e);

    float4 ps = *(const float4*)(v + pr.x * 32 + d * 4);
    float4 pd = *(const float4*)(v + pr.y * 32 + d * 4);

    // ---- conflict-free ρ-layout column reads from smem ----
    // Rs[row][d] of edge g at ws byte: g*256 + ((row^g)<<5) + d*4
    // Rd[row][d]                  at: 1024 + g*256 + ((row^g^4)<<5) + d*4
    float S[8], D[8];
    {
        unsigned q = (unsigned)((d & 3) ^ g);
        unsigned AS = (unsigned)(g * 256 + d * 4) + (q << 5);
        unsigned AD = AS + 1024u;
#pragma unroll
        for (int k = 0; k < 8; k++) {
            unsigned xs = ((unsigned)(k & 3) << 5);
            unsigned hiS = (k & 4) ? 128u : 0u;
            unsigned hiD = (k & 4) ? 0u : 128u;   // ^4 flips row bit 2
            S[k] = *(const float*)(ws + ((AS ^ xs) + hiS));
            D[k] = *(const float*)(ws + ((AD ^ xs) + hiD));
        }
    }

    // ---- fused z production + stage-1 exchange (peak z live ~5 float4) ----
    float4 z0, z2, z4, z6;
    {
        float4 a = zmk(S[0], D[0], ps, pd);
        float4 b = zmk(S[1], D[1], ps, pd);
        z0 = a; add4(z0, shfl4(b, 1, mask));
        a = zmk(S[2], D[2], ps, pd);
        b = zmk(S[3], D[3], ps, pd);
        z2 = a; add4(z2, shfl4(b, 1, mask));
        a = zmk(S[4], D[4], ps, pd);
        b = zmk(S[5], D[5], ps, pd);
        z4 = a; add4(z4, shfl4(b, 1, mask));
        a = zmk(S[6], D[6], ps, pd);
        b = zmk(S[7], D[7], ps, pd);
        z6 = a; add4(z6, shfl4(b, 1, mask));
    }
    // stage 2
    add4(z0, shfl4(z2, 2, mask));
    add4(z4, shfl4(z6, 2, mask));
    // stage 4 (self-exchange; rho invariant under d2)
    float4 R0 = z0; add4(R0, shfl4(z0, 4, mask));   // r[d01][:]
    float4 R1 = z4; add4(R1, shfl4(z4, 4, mask));   // r[d01+4][:]

    // ---- allgather + transpose matvec (local FMAs) ----
    float4 cs = make_float4(0.f, 0.f, 0.f, 0.f);
    float4 cd = make_float4(0.f, 0.f, 0.f, 0.f);
    fma4(cs, S[0], R0);  fma4(cs, S[4], R1);
    fma4(cd, D[0], R0);  fma4(cd, D[4], R1);
#pragma unroll
    for (int x = 1; x < 4; x++) {
        float4 r0x = shfl4(R0, x, mask);   // r[x^d01][:]
        float4 r1x = shfl4(R1, x, mask);   // r[(x^d01)+4][:]
        fma4(cs, S[x],     r0x);
        fma4(cd, D[x],     r0x);
        fma4(cs, S[x + 4], r1x);
        fma4(cd, D[x + 4], r1x);
    }

    red_add_v4(acc + pr.x * 32 + d * 4, cs);
    red_add_v4(acc + pr.y * 32 + d * 4,
               make_float4(-cd.x, -cd.y, -cd.z, -cd.w));
}

// ---------------------------------------------------------------------------
// update: out[b][m][d] += pc[k] * acc[m][d][b]; optionally zero other buffer
// ---------------------------------------------------------------------------
__global__ void update_kernel(const float* __restrict__ acc,
                              const float* __restrict__ pc,
                              int k,
                              float* __restrict__ out,
                              float* __restrict__ zother,
                              int M)
{
    int i = blockIdx.x * blockDim.x + threadIdx.x;
    int n = M * 32;
    if (i >= n) return;
    int m = i >> 5;
    int d = (i >> 2) & 7;
    int b = i & 3;
    float val = acc[i];
    int oi = (b * M + m) * 8 + d;
    out[oi] += pc[k] * val;
    if (zother) zother[i] = 0.0f;
}

// ---------------------------------------------------------------------------
// launch  (7 launches total; ncu -s 5 captures launch #6 = 3rd edge_kernel)
// ---------------------------------------------------------------------------
extern "C" void kernel_launch(void* const* d_in, const int* in_sizes, int n_in,
                              void* d_out, int out_size)
{
    const float* c0  = (const float*)d_in[0];
    const int*   src = (const int*)  d_in[1];
    const int*   dst = (const int*)  d_in[2];
    const float* Rs  = (const float*)d_in[3];
    const float* Rd  = (const float*)d_in[4];
    const float* pc  = (const float*)d_in[5];
    float* out = (float*)d_out;

    int E = in_sizes[1];
    int M = in_sizes[0] / (B_CONST * D_CONST);

    float* bufA;  float* bufB;  int2* pairp;
    cudaGetSymbolAddress((void**)&bufA,  g_bufA);
    cudaGetSymbolAddress((void**)&bufB,  g_bufB);
    cudaGetSymbolAddress((void**)&pairp, g_pair);

    int nV = M * 32;
    int tb = 256;
    int nInit = (nV > E) ? nV : E;
    int gI = (nInit + tb - 1) / tb;
    int gV = (nV + tb - 1) / tb;
    // 4 edges per warp = 32 edges per 256-thread block
    int gE = (E + 31) / 32;

    init_kernel<<<gI, tb>>>(c0, src, dst, pc, out, bufA, bufB, pairp, M, E);

    // k = 1: B <- L(A); out += pc[1]*B; zero A
    edge_kernel<<<gE, tb>>>(bufA, pairp, Rs, Rd, bufB, E);
    update_kernel<<<gV, tb>>>(bufB, pc, 1, out, bufA, M);

    // k = 2: A <- L(B); out += pc[2]*A; zero B
    edge_kernel<<<gE, tb>>>(bufB, pairp, Rs, Rd, bufA, E);
    update_kernel<<<gV, tb>>>(bufA, pc, 2, out, bufB, M);

    // k = 3: B <- L(A); out += pc[3]*B
    edge_kernel<<<gE, tb>>>(bufA, pairp, Rs, Rd, bufB, E);
    update_kernel<<<gV, tb>>>(bufB, pc, 3, out, nullptr, M);
}